// round 5
// baseline (speedup 1.0000x reference)
#include <cuda_runtime.h>
#include <math.h>

#define S_ 32
#define H_ 768
#define I_ 768
#define E_ 32
#define TOPK_ 4
#define LIMIT_ 7.0f
#define ALPHA_ 1.702f
#define EPS_ 1e-5f

#define TB 8           // max tokens per work chunk
#define MAXW 64        // max work chunks
#define HV4 (H_ / 4)   // 192 float4 per row

// Scratch (device globals: allocation-free)
__device__ float g_t[S_ * H_];           // rmsnormed tokens
__device__ int   g_idx[S_ * TOPK_];      // top-k expert ids
__device__ float g_wts[S_ * TOPK_];      // softmax weights
__device__ int   g_cnt[E_];              // tokens per expert
__device__ int   g_sel[E_ * S_];         // sel = s*4+k per expert slot
__device__ float g_act[S_ * TOPK_ * I_]; // post-SwiGLU activations
__device__ int   g_work[MAXW * 3];       // (expert, base, len)
__device__ int   g_nw;

// Packed reduction: 4 per-thread partials -> lane L (L<4) holds full sum of a[L].
__device__ __forceinline__ float reduce4(float a0, float a1, float a2, float a3, int lane)
{
    float w0 = (lane & 1) ? a1 : a0;
    float o0 = (lane & 1) ? a0 : a1;
    float b0 = w0 + __shfl_xor_sync(0xffffffffu, o0, 1);
    float w1 = (lane & 1) ? a3 : a2;
    float o1 = (lane & 1) ? a2 : a3;
    float b1 = w1 + __shfl_xor_sync(0xffffffffu, o1, 1);
    float w2 = (lane & 2) ? b1 : b0;
    float o2 = (lane & 2) ? b0 : b1;
    float c  = w2 + __shfl_xor_sync(0xffffffffu, o2, 2);
    c += __shfl_xor_sync(0xffffffffu, c, 4);
    c += __shfl_xor_sync(0xffffffffu, c, 8);
    c += __shfl_xor_sync(0xffffffffu, c, 16);
    return c;
}

// 4 weight rows x NT tokens dot-product core. wp = row r0 base (float4),
// rows at stride 192 float4. sm = token tile (NT rows zero-padded).
template<int NT>
__device__ __forceinline__ void dot_rows4(
    const float4* __restrict__ wp, const float* __restrict__ sm,
    int lane, float acc[4][TB])
{
#pragma unroll
    for (int q = 0; q < 6; q++) {
        float4 w0 = wp[          lane + 32 * q];
        float4 w1 = wp[1 * 192 + lane + 32 * q];
        float4 w2 = wp[2 * 192 + lane + 32 * q];
        float4 w3 = wp[3 * 192 + lane + 32 * q];
#pragma unroll
        for (int i = 0; i < NT; i++) {
            float4 tv = ((const float4*)sm)[i * 192 + lane + 32 * q];
            acc[0][i] += w0.x * tv.x + w0.y * tv.y + w0.z * tv.z + w0.w * tv.w;
            acc[1][i] += w1.x * tv.x + w1.y * tv.y + w1.z * tv.z + w1.w * tv.w;
            acc[2][i] += w2.x * tv.x + w2.y * tv.y + w2.z * tv.z + w2.w * tv.w;
            acc[3][i] += w3.x * tv.x + w3.y * tv.y + w3.z * tv.z + w3.w * tv.w;
        }
    }
}

// ---------------------------------------------------------------------------
// Kernel 1: RMSNorm + router (logits, top-4, softmax) + residual init
// ---------------------------------------------------------------------------
__global__ void __launch_bounds__(256) k_norm_router(
    const float* __restrict__ x, const float* __restrict__ nscale,
    const float* __restrict__ gw, const float* __restrict__ gb,
    float* __restrict__ out)
{
    int s   = blockIdx.x;
    int tid = threadIdx.x;
    int lane = tid & 31, wid = tid >> 5;

    __shared__ float sh_t[H_];
    __shared__ float red[8];
    __shared__ float logits[E_];

    float v0[3];
    float ss = 0.f;
#pragma unroll
    for (int q = 0; q < 3; q++) {
        float v = x[s * H_ + tid + 256 * q];
        v0[q] = v;
        ss += v * v;
    }
#pragma unroll
    for (int o = 16; o; o >>= 1) ss += __shfl_xor_sync(0xffffffffu, ss, o);
    if (lane == 0) red[wid] = ss;
    __syncthreads();
    if (tid < 8) {
        float r = red[tid];
#pragma unroll
        for (int o = 4; o; o >>= 1) r += __shfl_xor_sync(0xffu, r, o);
        if (tid == 0) red[0] = r;
    }
    __syncthreads();
    float rms = rsqrtf(red[0] / (float)H_ + EPS_);

#pragma unroll
    for (int q = 0; q < 3; q++) {
        int j = tid + 256 * q;
        float t = v0[q] * rms * nscale[j];
        sh_t[j] = t;
        g_t[s * H_ + j] = t;
        out[s * H_ + j] = v0[q];   // residual init out = x
    }
    __syncthreads();

#pragma unroll
    for (int e4 = 0; e4 < 4; e4++) {
        int e = wid * 4 + e4;
        float acc = 0.f;
        for (int j = lane; j < H_; j += 32) acc += sh_t[j] * gw[e * H_ + j];
#pragma unroll
        for (int o = 16; o; o >>= 1) acc += __shfl_xor_sync(0xffffffffu, acc, o);
        if (lane == 0) logits[e] = acc + gb[e];
    }
    __syncthreads();

    if (tid == 0) {
        float l[E_];
#pragma unroll
        for (int e = 0; e < E_; e++) l[e] = logits[e];
        float vals[TOPK_];
        int   ids[TOPK_];
#pragma unroll
        for (int k = 0; k < TOPK_; k++) {
            float m = -1e30f; int mi = 0;
            for (int e = 0; e < E_; e++) {
                if (l[e] > m) { m = l[e]; mi = e; }
            }
            vals[k] = m; ids[k] = mi; l[mi] = -1e30f;
        }
        float mx = vals[0], sum = 0.f, w[TOPK_];
#pragma unroll
        for (int k = 0; k < TOPK_; k++) { w[k] = __expf(vals[k] - mx); sum += w[k]; }
        float inv = 1.f / sum;
#pragma unroll
        for (int k = 0; k < TOPK_; k++) {
            g_idx[s * TOPK_ + k] = ids[k];
            g_wts[s * TOPK_ + k] = w[k] * inv;
        }
    }
}

// ---------------------------------------------------------------------------
// Kernel 2: build per-expert selection lists + work chunks (single thread)
// ---------------------------------------------------------------------------
__global__ void k_build()
{
    if (threadIdx.x == 0 && blockIdx.x == 0) {
        for (int e = 0; e < E_; e++) g_cnt[e] = 0;
        for (int sel = 0; sel < S_ * TOPK_; sel++) {
            int e = g_idx[sel];
            g_sel[e * S_ + g_cnt[e]] = sel;
            g_cnt[e]++;
        }
        int w = 0;
        for (int e = 0; e < E_; e++) {
            int n = g_cnt[e];
            for (int base = 0; base < n; base += TB) {
                int len = n - base; if (len > TB) len = TB;
                g_work[w * 3 + 0] = e;
                g_work[w * 3 + 1] = base;
                g_work[w * 3 + 2] = len;
                w++;
            }
        }
        g_nw = w;
    }
}

// ---------------------------------------------------------------------------
// Kernel 3: expert MLP-1 (raw rows, 4-row register blocking) + SwiGLU epilogue
// grid (2I_/32, MAXW), 256 threads; warp wid -> rows rbase + 4*wid .. +3
// ---------------------------------------------------------------------------
#define T1R 32
__global__ void __launch_bounds__(256) k_mlp1(
    const float* __restrict__ w1, const float* __restrict__ b1)
{
    int widx = blockIdx.y;
    if (widx >= g_nw) return;
    int e    = g_work[widx * 3 + 0];
    int base = g_work[widx * 3 + 1];
    int n    = g_work[widx * 3 + 2];
    int npad = (n <= 4) ? 4 : 8;

    __shared__ float sm[TB * H_];       // 24 KB token tile (zero-padded)
    __shared__ float sh_h[TB][T1R];     // raw pre-activations
    __shared__ int ssel[TB];

    int tid = threadIdx.x, wid = tid >> 5, lane = tid & 31;

    if (tid < n) ssel[tid] = g_sel[e * S_ + base + tid];
    __syncthreads();
    for (int i = 0; i < npad; i++) {
        if (i < n) {
            int s = ssel[i] >> 2;
            for (int j = tid; j < H_; j += 256) sm[i * H_ + j] = g_t[s * H_ + j];
        } else {
            for (int j = tid; j < H_; j += 256) sm[i * H_ + j] = 0.f;
        }
    }
    __syncthreads();

    int rbase = blockIdx.x * T1R;
    int r0 = rbase + wid * 4;
    const float4* wp = (const float4*)(w1 + ((size_t)e * 2 * I_ + r0) * H_);
    float bias[4];
#pragma unroll
    for (int j = 0; j < 4; j++) bias[j] = b1[e * 2 * I_ + r0 + j];

    float acc[4][TB];
#pragma unroll
    for (int j = 0; j < 4; j++)
#pragma unroll
        for (int i = 0; i < TB; i++) acc[j][i] = 0.f;

    if (n <= 4) dot_rows4<4>(wp, sm, lane, acc);
    else        dot_rows4<8>(wp, sm, lane, acc);

#pragma unroll
    for (int j = 0; j < 4; j++) {
        float d = reduce4(acc[j][0], acc[j][1], acc[j][2], acc[j][3], lane);
        if (lane < 4 && lane < n) sh_h[lane][wid * 4 + j] = d + bias[j];
    }
    if (n > 4) {
#pragma unroll
        for (int j = 0; j < 4; j++) {
            float d = reduce4(acc[j][4], acc[j][5], acc[j][6], acc[j][7], lane);
            if (lane < 4 && 4 + lane < n) sh_h[4 + lane][wid * 4 + j] = d + bias[j];
        }
    }
    __syncthreads();

    // epilogue: combine (gate, linear) pairs -> act
    int items = n * (T1R / 2);
    for (int it = tid; it < items; it += 256) {
        int i = it / (T1R / 2);
        int m = it % (T1R / 2);
        float hg = sh_h[i][2 * m];
        float hl = sh_h[i][2 * m + 1];
        hg = fminf(hg, LIMIT_);
        hl = fminf(fmaxf(hl, -LIMIT_), LIMIT_);
        float sig = 1.f / (1.f + __expf(-ALPHA_ * hg));
        int c = (rbase >> 1) + m;
        g_act[ssel[i] * I_ + c] = hg * sig * (hl + 1.f);
    }
}

// ---------------------------------------------------------------------------
// Kernel 4: expert MLP-2 (4-row register blocking) + weighted accumulation
// grid (H_/32, MAXW), 256 threads; warp wid -> rows cbase + 4*wid .. +3
// ---------------------------------------------------------------------------
#define T2C 32
__global__ void __launch_bounds__(256) k_mlp2(
    const float* __restrict__ w2, const float* __restrict__ b2,
    float* __restrict__ out)
{
    int widx = blockIdx.y;
    if (widx >= g_nw) return;
    int e    = g_work[widx * 3 + 0];
    int base = g_work[widx * 3 + 1];
    int n    = g_work[widx * 3 + 2];
    int npad = (n <= 4) ? 4 : 8;

    __shared__ float sm[TB * I_];     // 24 KB act tile (zero-padded)
    __shared__ int   ssel[TB];
    __shared__ float swt[TB];

    int tid = threadIdx.x, wid = tid >> 5, lane = tid & 31;

    if (tid < n) {
        int sel = g_sel[e * S_ + base + tid];
        ssel[tid] = sel;
        swt[tid]  = g_wts[sel];
    }
    __syncthreads();
    for (int i = 0; i < npad; i++) {
        if (i < n) {
            int sel = ssel[i];
            for (int j = tid; j < I_; j += 256) sm[i * I_ + j] = g_act[sel * I_ + j];
        } else {
            for (int j = tid; j < I_; j += 256) sm[i * I_ + j] = 0.f;
        }
    }
    __syncthreads();

    int cbase = blockIdx.x * T2C;
    int c0 = cbase + wid * 4;
    const float4* wp = (const float4*)(w2 + ((size_t)e * H_ + c0) * I_);
    float bias[4];
#pragma unroll
    for (int j = 0; j < 4; j++) bias[j] = b2[e * H_ + c0 + j];

    float acc[4][TB];
#pragma unroll
    for (int j = 0; j < 4; j++)
#pragma unroll
        for (int i = 0; i < TB; i++) acc[j][i] = 0.f;

    if (n <= 4) dot_rows4<4>(wp, sm, lane, acc);
    else        dot_rows4<8>(wp, sm, lane, acc);

#pragma unroll
    for (int j = 0; j < 4; j++) {
        float d = reduce4(acc[j][0], acc[j][1], acc[j][2], acc[j][3], lane);
        if (lane < 4 && lane < n) {
            int s = ssel[lane] >> 2;
            atomicAdd(&out[s * H_ + c0 + j], swt[lane] * (d + bias[j]));
        }
    }
    if (n > 4) {
#pragma unroll
        for (int j = 0; j < 4; j++) {
            float d = reduce4(acc[j][4], acc[j][5], acc[j][6], acc[j][7], lane);
            if (lane < 4 && 4 + lane < n) {
                int s = ssel[4 + lane] >> 2;
                atomicAdd(&out[s * H_ + c0 + j], swt[4 + lane] * (d + bias[j]));
            }
        }
    }
}

// ---------------------------------------------------------------------------
extern "C" void kernel_launch(void* const* d_in, const int* in_sizes, int n_in,
                              void* d_out, int out_size)
{
    const float* x  = (const float*)d_in[0];
    const float* ns = (const float*)d_in[1];
    const float* gw = (const float*)d_in[2];
    const float* gb = (const float*)d_in[3];
    const float* w1 = (const float*)d_in[4];
    const float* b1 = (const float*)d_in[5];
    const float* w2 = (const float*)d_in[6];
    const float* b2 = (const float*)d_in[7];
    float* out = (float*)d_out;

    k_norm_router<<<S_, 256>>>(x, ns, gw, gb, out);
    k_build<<<1, 32>>>();
    dim3 g1(2 * I_ / T1R, MAXW);   // (48, 64)
    k_mlp1<<<g1, 256>>>(w1, b1);
    dim3 g2(H_ / T2C, MAXW);       // (24, 64)
    k_mlp2<<<g2, 256>>>(w2, b2, out);
}

// round 6
// speedup vs baseline: 1.0486x; 1.0486x over previous
#include <cuda_runtime.h>
#include <math.h>

#define S_ 32
#define H_ 768
#define I_ 768
#define E_ 32
#define TOPK_ 4
#define LIMIT_ 7.0f
#define ALPHA_ 1.702f
#define EPS_ 1e-5f

#define TB 8           // max tokens per work chunk
#define MAXW 64        // max work chunks
#define HV4 (H_ / 4)   // 192 float4 per row

// Scratch (device globals: allocation-free)
__device__ float g_t[S_ * H_];           // rmsnormed tokens
__device__ int   g_idx[S_ * TOPK_];      // top-k expert ids
__device__ float g_wts[S_ * TOPK_];      // softmax weights
__device__ int   g_cnt[E_];              // tokens per expert
__device__ int   g_sel[E_ * S_];         // sel = s*4+k per expert slot
__device__ float g_act[S_ * TOPK_ * I_]; // post-SwiGLU activations
__device__ int   g_work[MAXW * 3];       // (expert, base, len)
__device__ int   g_nw;

// ---- f32x2 packed math helpers -------------------------------------------
__device__ __forceinline__ unsigned long long pack2dup(float x)
{
    unsigned long long r;
    unsigned int u = __float_as_uint(x);
    asm("mov.b64 %0, {%1, %1};" : "=l"(r) : "r"(u));
    return r;
}
__device__ __forceinline__ void ffma2(unsigned long long& acc,
                                      unsigned long long a, unsigned long long b)
{
    asm("fma.rn.f32x2 %0, %1, %2, %0;" : "+l"(acc) : "l"(a), "l"(b));
}
__device__ __forceinline__ float2 unpack2(unsigned long long v)
{
    unsigned int lo, hi;
    asm("mov.b64 {%0, %1}, %2;" : "=r"(lo), "=r"(hi) : "l"(v));
    return make_float2(__uint_as_float(lo), __uint_as_float(hi));
}

// Packed reduction: 4 per-thread partials -> lane L (L<4) holds full sum of a[L].
__device__ __forceinline__ float reduce4(float a0, float a1, float a2, float a3, int lane)
{
    float w0 = (lane & 1) ? a1 : a0;
    float o0 = (lane & 1) ? a0 : a1;
    float b0 = w0 + __shfl_xor_sync(0xffffffffu, o0, 1);
    float w1 = (lane & 1) ? a3 : a2;
    float o1 = (lane & 1) ? a2 : a3;
    float b1 = w1 + __shfl_xor_sync(0xffffffffu, o1, 1);
    float w2 = (lane & 2) ? b1 : b0;
    float o2 = (lane & 2) ? b0 : b1;
    float c  = w2 + __shfl_xor_sync(0xffffffffu, o2, 2);
    c += __shfl_xor_sync(0xffffffffu, c, 4);
    c += __shfl_xor_sync(0xffffffffu, c, 8);
    c += __shfl_xor_sync(0xffffffffu, c, 16);
    return c;
}

// 2 weight rows x NP token-pairs core. Weights streamed from gmem (one q-step
// at a time, unroll 1 keeps LDG live range short); tokens from smem pairs.
template<int NP>
__device__ __forceinline__ void core2(
    const float4* __restrict__ wp0, const float4* __restrict__ wp1,
    const float2* __restrict__ pairs, int lane, unsigned long long acc[2][4])
{
#pragma unroll 1
    for (int q = 0; q < 6; q++) {
        float4 wa = wp0[lane + 32 * q];
        float4 wb = wp1[lane + 32 * q];
        unsigned long long da0 = pack2dup(wa.x), da1 = pack2dup(wa.y);
        unsigned long long da2 = pack2dup(wa.z), da3 = pack2dup(wa.w);
        unsigned long long db0 = pack2dup(wb.x), db1 = pack2dup(wb.y);
        unsigned long long db2 = pack2dup(wb.z), db3 = pack2dup(wb.w);
#pragma unroll
        for (int p = 0; p < NP; p++) {
            const ulonglong2* pp =
                (const ulonglong2*)(pairs + (size_t)p * H_ + 4 * (lane + 32 * q));
            ulonglong2 u0 = pp[0];   // pairs for j, j+1
            ulonglong2 u1 = pp[1];   // pairs for j+2, j+3
            ffma2(acc[0][p], da0, u0.x); ffma2(acc[1][p], db0, u0.x);
            ffma2(acc[0][p], da1, u0.y); ffma2(acc[1][p], db1, u0.y);
            ffma2(acc[0][p], da2, u1.x); ffma2(acc[1][p], db2, u1.x);
            ffma2(acc[0][p], da3, u1.y); ffma2(acc[1][p], db3, u1.y);
        }
    }
}

// ---------------------------------------------------------------------------
// Kernel 1: RMSNorm + router (logits, top-4, softmax) + residual init
// ---------------------------------------------------------------------------
__global__ void __launch_bounds__(256) k_norm_router(
    const float* __restrict__ x, const float* __restrict__ nscale,
    const float* __restrict__ gw, const float* __restrict__ gb,
    float* __restrict__ out)
{
    int s   = blockIdx.x;
    int tid = threadIdx.x;
    int lane = tid & 31, wid = tid >> 5;

    __shared__ float sh_t[H_];
    __shared__ float red[8];
    __shared__ float logits[E_];

    float v0[3];
    float ss = 0.f;
#pragma unroll
    for (int q = 0; q < 3; q++) {
        float v = x[s * H_ + tid + 256 * q];
        v0[q] = v;
        ss += v * v;
    }
#pragma unroll
    for (int o = 16; o; o >>= 1) ss += __shfl_xor_sync(0xffffffffu, ss, o);
    if (lane == 0) red[wid] = ss;
    __syncthreads();
    if (tid < 8) {
        float r = red[tid];
#pragma unroll
        for (int o = 4; o; o >>= 1) r += __shfl_xor_sync(0xffu, r, o);
        if (tid == 0) red[0] = r;
    }
    __syncthreads();
    float rms = rsqrtf(red[0] / (float)H_ + EPS_);

#pragma unroll
    for (int q = 0; q < 3; q++) {
        int j = tid + 256 * q;
        float t = v0[q] * rms * nscale[j];
        sh_t[j] = t;
        g_t[s * H_ + j] = t;
        out[s * H_ + j] = v0[q];   // residual init out = x
    }
    __syncthreads();

#pragma unroll
    for (int e4 = 0; e4 < 4; e4++) {
        int e = wid * 4 + e4;
        float acc = 0.f;
        for (int j = lane; j < H_; j += 32) acc += sh_t[j] * gw[e * H_ + j];
#pragma unroll
        for (int o = 16; o; o >>= 1) acc += __shfl_xor_sync(0xffffffffu, acc, o);
        if (lane == 0) logits[e] = acc + gb[e];
    }
    __syncthreads();

    if (tid == 0) {
        float l[E_];
#pragma unroll
        for (int e = 0; e < E_; e++) l[e] = logits[e];
        float vals[TOPK_];
        int   ids[TOPK_];
#pragma unroll
        for (int k = 0; k < TOPK_; k++) {
            float m = -1e30f; int mi = 0;
            for (int e = 0; e < E_; e++) {
                if (l[e] > m) { m = l[e]; mi = e; }
            }
            vals[k] = m; ids[k] = mi; l[mi] = -1e30f;
        }
        float mx = vals[0], sum = 0.f, w[TOPK_];
#pragma unroll
        for (int k = 0; k < TOPK_; k++) { w[k] = __expf(vals[k] - mx); sum += w[k]; }
        float inv = 1.f / sum;
#pragma unroll
        for (int k = 0; k < TOPK_; k++) {
            g_idx[s * TOPK_ + k] = ids[k];
            g_wts[s * TOPK_ + k] = w[k] * inv;
        }
    }
}

// ---------------------------------------------------------------------------
// Kernel 2: build per-expert selection lists + work chunks (single thread)
// ---------------------------------------------------------------------------
__global__ void k_build()
{
    if (threadIdx.x == 0 && blockIdx.x == 0) {
        for (int e = 0; e < E_; e++) g_cnt[e] = 0;
        for (int sel = 0; sel < S_ * TOPK_; sel++) {
            int e = g_idx[sel];
            g_sel[e * S_ + g_cnt[e]] = sel;
            g_cnt[e]++;
        }
        int w = 0;
        for (int e = 0; e < E_; e++) {
            int n = g_cnt[e];
            for (int base = 0; base < n; base += TB) {
                int len = n - base; if (len > TB) len = TB;
                g_work[w * 3 + 0] = e;
                g_work[w * 3 + 1] = base;
                g_work[w * 3 + 2] = len;
                w++;
            }
        }
        g_nw = w;
    }
}

// ---------------------------------------------------------------------------
// Kernel 3: expert MLP-1 (raw rows, f32x2, 2-row blocking) + SwiGLU epilogue
// grid (2I_/32, MAXW), 256 threads; warp wid -> rows {jj*16 + wid*2, +1}
// ---------------------------------------------------------------------------
#define T1R 32
__global__ void __launch_bounds__(256, 4) k_mlp1(
    const float* __restrict__ w1, const float* __restrict__ b1)
{
    int widx = blockIdx.y;
    if (widx >= g_nw) return;
    int e    = g_work[widx * 3 + 0];
    int base = g_work[widx * 3 + 1];
    int n    = g_work[widx * 3 + 2];
    int NPp  = (n <= 4) ? 2 : 4;     // token pairs

    __shared__ float2 smp[4 * H_];      // 24 KB paired token tile
    __shared__ float sh_h[TB][T1R];     // raw pre-activations
    __shared__ int ssel[TB];

    int tid = threadIdx.x, wid = tid >> 5, lane = tid & 31;

    if (tid < n) ssel[tid] = g_sel[e * S_ + base + tid];
    __syncthreads();
    for (int p = 0; p < NPp; p++) {
        int ia = 2 * p, ib = 2 * p + 1;
        int sa = (ia < n) ? (ssel[ia] >> 2) : 0;
        int sb = (ib < n) ? (ssel[ib] >> 2) : 0;
        bool va = ia < n, vb = ib < n;
        for (int j = tid; j < H_; j += 256) {
            float fa = va ? g_t[sa * H_ + j] : 0.f;
            float fb = vb ? g_t[sb * H_ + j] : 0.f;
            smp[p * H_ + j] = make_float2(fa, fb);
        }
    }
    __syncthreads();

    int rbase = blockIdx.x * T1R;
#pragma unroll
    for (int jj = 0; jj < 2; jj++) {
        int rloc = jj * 16 + wid * 2;
        int r0 = rbase + rloc;
        const float4* wp0 = (const float4*)(w1 + ((size_t)e * 2 * I_ + r0) * H_);
        const float4* wp1 = wp0 + HV4;

        unsigned long long acc[2][4];
#pragma unroll
        for (int r = 0; r < 2; r++)
#pragma unroll
            for (int p = 0; p < 4; p++) acc[r][p] = 0ull;

        if (NPp == 2) core2<2>(wp0, wp1, smp, lane, acc);
        else          core2<4>(wp0, wp1, smp, lane, acc);

#pragma unroll
        for (int r = 0; r < 2; r++) {
            float bias = b1[e * 2 * I_ + r0 + r];
            float2 p0 = unpack2(acc[r][0]);
            float2 p1 = unpack2(acc[r][1]);
            float d = reduce4(p0.x, p0.y, p1.x, p1.y, lane);
            if (lane < 4 && lane < n) sh_h[lane][rloc + r] = d + bias;
            if (NPp == 4) {
                float2 p2 = unpack2(acc[r][2]);
                float2 p3 = unpack2(acc[r][3]);
                float d2 = reduce4(p2.x, p2.y, p3.x, p3.y, lane);
                if (lane < 4 && 4 + lane < n) sh_h[4 + lane][rloc + r] = d2 + bias;
            }
        }
    }
    __syncthreads();

    // epilogue: combine (gate, linear) pairs -> act
    int items = n * (T1R / 2);
    for (int it = tid; it < items; it += 256) {
        int i = it / (T1R / 2);
        int m = it % (T1R / 2);
        float hg = sh_h[i][2 * m];
        float hl = sh_h[i][2 * m + 1];
        hg = fminf(hg, LIMIT_);
        hl = fminf(fmaxf(hl, -LIMIT_), LIMIT_);
        float sig = 1.f / (1.f + __expf(-ALPHA_ * hg));
        int c = (rbase >> 1) + m;
        g_act[ssel[i] * I_ + c] = hg * sig * (hl + 1.f);
    }
}

// ---------------------------------------------------------------------------
// Kernel 4: expert MLP-2 (f32x2, 2-row blocking) + weighted accumulation
// grid (H_/32, MAXW), 256 threads
// ---------------------------------------------------------------------------
#define T2C 32
__global__ void __launch_bounds__(256, 4) k_mlp2(
    const float* __restrict__ w2, const float* __restrict__ b2,
    float* __restrict__ out)
{
    int widx = blockIdx.y;
    if (widx >= g_nw) return;
    int e    = g_work[widx * 3 + 0];
    int base = g_work[widx * 3 + 1];
    int n    = g_work[widx * 3 + 2];
    int NPp  = (n <= 4) ? 2 : 4;

    __shared__ float2 smp[4 * I_];    // 24 KB paired act tile
    __shared__ int   ssel[TB];
    __shared__ float swt[TB];

    int tid = threadIdx.x, wid = tid >> 5, lane = tid & 31;

    if (tid < n) {
        int sel = g_sel[e * S_ + base + tid];
        ssel[tid] = sel;
        swt[tid]  = g_wts[sel];
    }
    __syncthreads();
    for (int p = 0; p < NPp; p++) {
        int ia = 2 * p, ib = 2 * p + 1;
        int sela = (ia < n) ? ssel[ia] : 0;
        int selb = (ib < n) ? ssel[ib] : 0;
        bool va = ia < n, vb = ib < n;
        for (int j = tid; j < I_; j += 256) {
            float fa = va ? g_act[sela * I_ + j] : 0.f;
            float fb = vb ? g_act[selb * I_ + j] : 0.f;
            smp[p * I_ + j] = make_float2(fa, fb);
        }
    }
    __syncthreads();

    int cbase = blockIdx.x * T2C;
#pragma unroll
    for (int jj = 0; jj < 2; jj++) {
        int c0 = cbase + jj * 16 + wid * 2;
        const float4* wp0 = (const float4*)(w2 + ((size_t)e * H_ + c0) * I_);
        const float4* wp1 = wp0 + (I_ / 4);

        unsigned long long acc[2][4];
#pragma unroll
        for (int r = 0; r < 2; r++)
#pragma unroll
            for (int p = 0; p < 4; p++) acc[r][p] = 0ull;

        if (NPp == 2) core2<2>(wp0, wp1, smp, lane, acc);
        else          core2<4>(wp0, wp1, smp, lane, acc);

#pragma unroll
        for (int r = 0; r < 2; r++) {
            float bias = b2[e * H_ + c0 + r];
            float2 p0 = unpack2(acc[r][0]);
            float2 p1 = unpack2(acc[r][1]);
            float d = reduce4(p0.x, p0.y, p1.x, p1.y, lane);
            if (lane < 4 && lane < n) {
                int s = ssel[lane] >> 2;
                atomicAdd(&out[s * H_ + c0 + r], swt[lane] * (d + bias));
            }
            if (NPp == 4) {
                float2 p2 = unpack2(acc[r][2]);
                float2 p3 = unpack2(acc[r][3]);
                float d2 = reduce4(p2.x, p2.y, p3.x, p3.y, lane);
                if (lane < 4 && 4 + lane < n) {
                    int s = ssel[4 + lane] >> 2;
                    atomicAdd(&out[s * H_ + c0 + r], swt[4 + lane] * (d2 + bias));
                }
            }
        }
    }
}

// ---------------------------------------------------------------------------
extern "C" void kernel_launch(void* const* d_in, const int* in_sizes, int n_in,
                              void* d_out, int out_size)
{
    const float* x  = (const float*)d_in[0];
    const float* ns = (const float*)d_in[1];
    const float* gw = (const float*)d_in[2];
    const float* gb = (const float*)d_in[3];
    const float* w1 = (const float*)d_in[4];
    const float* b1 = (const float*)d_in[5];
    const float* w2 = (const float*)d_in[6];
    const float* b2 = (const float*)d_in[7];
    float* out = (float*)d_out;

    k_norm_router<<<S_, 256>>>(x, ns, gw, gb, out);
    k_build<<<1, 32>>>();
    dim3 g1(2 * I_ / T1R, MAXW);   // (48, 64)
    k_mlp1<<<g1, 256>>>(w1, b1);
    dim3 g2(H_ / T2C, MAXW);       // (24, 64)
    k_mlp2<<<g2, 256>>>(w2, b2, out);
}

// round 7
// speedup vs baseline: 1.2704x; 1.2115x over previous
#include <cuda_runtime.h>
#include <math.h>

#define S_ 32
#define H_ 768
#define I_ 768
#define E_ 32
#define TOPK_ 4
#define LIMIT_ 7.0f
#define ALPHA_ 1.702f
#define EPS_ 1e-5f

#define TB 4           // max tokens per work chunk (fits acc[4][4])
#define MAXW 64        // max work chunks (worst case 56)
#define HV4 (H_ / 4)   // 192 float4 per row

// Scratch (device globals: allocation-free)
__device__ float g_t[S_ * H_];           // rmsnormed tokens
__device__ int   g_idx[S_ * TOPK_];      // top-k expert ids
__device__ float g_wts[S_ * TOPK_];      // softmax weights
__device__ int   g_cnt[E_];              // tokens per expert
__device__ int   g_sel[E_ * S_];         // sel = s*4+k per expert slot
__device__ float g_act[S_ * TOPK_ * I_]; // post-SwiGLU activations
__device__ int   g_work[MAXW * 3];       // (expert, base, len)
__device__ int   g_nw;

// Packed reduction: 4 per-thread partials -> lane L (L<4) holds full sum of a[L].
__device__ __forceinline__ float reduce4(float a0, float a1, float a2, float a3, int lane)
{
    float w0 = (lane & 1) ? a1 : a0;
    float o0 = (lane & 1) ? a0 : a1;
    float b0 = w0 + __shfl_xor_sync(0xffffffffu, o0, 1);
    float w1 = (lane & 1) ? a3 : a2;
    float o1 = (lane & 1) ? a2 : a3;
    float b1 = w1 + __shfl_xor_sync(0xffffffffu, o1, 1);
    float w2 = (lane & 2) ? b1 : b0;
    float o2 = (lane & 2) ? b0 : b1;
    float c  = w2 + __shfl_xor_sync(0xffffffffu, o2, 2);
    c += __shfl_xor_sync(0xffffffffu, c, 4);
    c += __shfl_xor_sync(0xffffffffu, c, 8);
    c += __shfl_xor_sync(0xffffffffu, c, 16);
    return c;
}

// 4 weight rows (stride 192 float4) x 4 tokens from smem tile.
__device__ __forceinline__ void core44(
    const float4* __restrict__ wp, const float* __restrict__ tile,
    int lane, float acc[4][4])
{
#pragma unroll 2
    for (int q = 0; q < 6; q++) {
        float4 w[4], t[4];
#pragma unroll
        for (int r = 0; r < 4; r++) w[r] = wp[r * 192 + lane + 32 * q];
#pragma unroll
        for (int i = 0; i < 4; i++) t[i] = ((const float4*)tile)[i * 192 + lane + 32 * q];
#pragma unroll
        for (int r = 0; r < 4; r++)
#pragma unroll
            for (int i = 0; i < 4; i++)
                acc[r][i] += w[r].x * t[i].x + w[r].y * t[i].y
                           + w[r].z * t[i].z + w[r].w * t[i].w;
    }
}

// ---------------------------------------------------------------------------
// Kernel 1: RMSNorm + router (logits, top-4, softmax) + residual init
// ---------------------------------------------------------------------------
__global__ void __launch_bounds__(256) k_norm_router(
    const float* __restrict__ x, const float* __restrict__ nscale,
    const float* __restrict__ gw, const float* __restrict__ gb,
    float* __restrict__ out)
{
    int s   = blockIdx.x;
    int tid = threadIdx.x;
    int lane = tid & 31, wid = tid >> 5;

    __shared__ float sh_t[H_];
    __shared__ float red[8];
    __shared__ float logits[E_];

    float v0[3];
    float ss = 0.f;
#pragma unroll
    for (int q = 0; q < 3; q++) {
        float v = x[s * H_ + tid + 256 * q];
        v0[q] = v;
        ss += v * v;
    }
#pragma unroll
    for (int o = 16; o; o >>= 1) ss += __shfl_xor_sync(0xffffffffu, ss, o);
    if (lane == 0) red[wid] = ss;
    __syncthreads();
    if (tid < 8) {
        float r = red[tid];
#pragma unroll
        for (int o = 4; o; o >>= 1) r += __shfl_xor_sync(0xffu, r, o);
        if (tid == 0) red[0] = r;
    }
    __syncthreads();
    float rms = rsqrtf(red[0] / (float)H_ + EPS_);

#pragma unroll
    for (int q = 0; q < 3; q++) {
        int j = tid + 256 * q;
        float t = v0[q] * rms * nscale[j];
        sh_t[j] = t;
        g_t[s * H_ + j] = t;
        out[s * H_ + j] = v0[q];   // residual init out = x
    }
    __syncthreads();

#pragma unroll
    for (int e4 = 0; e4 < 4; e4++) {
        int e = wid * 4 + e4;
        float acc = 0.f;
        for (int j = lane; j < H_; j += 32) acc += sh_t[j] * gw[e * H_ + j];
#pragma unroll
        for (int o = 16; o; o >>= 1) acc += __shfl_xor_sync(0xffffffffu, acc, o);
        if (lane == 0) logits[e] = acc + gb[e];
    }
    __syncthreads();

    if (tid == 0) {
        float l[E_];
#pragma unroll
        for (int e = 0; e < E_; e++) l[e] = logits[e];
        float vals[TOPK_];
        int   ids[TOPK_];
#pragma unroll
        for (int k = 0; k < TOPK_; k++) {
            float m = -1e30f; int mi = 0;
            for (int e = 0; e < E_; e++) {
                if (l[e] > m) { m = l[e]; mi = e; }
            }
            vals[k] = m; ids[k] = mi; l[mi] = -1e30f;
        }
        float mx = vals[0], sum = 0.f, w[TOPK_];
#pragma unroll
        for (int k = 0; k < TOPK_; k++) { w[k] = __expf(vals[k] - mx); sum += w[k]; }
        float inv = 1.f / sum;
#pragma unroll
        for (int k = 0; k < TOPK_; k++) {
            g_idx[s * TOPK_ + k] = ids[k];
            g_wts[s * TOPK_ + k] = w[k] * inv;
        }
    }
}

// ---------------------------------------------------------------------------
// Kernel 2: build per-expert selection lists + work chunks (single thread)
// ---------------------------------------------------------------------------
__global__ void k_build()
{
    if (threadIdx.x == 0 && blockIdx.x == 0) {
        for (int e = 0; e < E_; e++) g_cnt[e] = 0;
        for (int sel = 0; sel < S_ * TOPK_; sel++) {
            int e = g_idx[sel];
            g_sel[e * S_ + g_cnt[e]] = sel;
            g_cnt[e]++;
        }
        int w = 0;
        for (int e = 0; e < E_; e++) {
            int n = g_cnt[e];
            for (int base = 0; base < n; base += TB) {
                int len = n - base; if (len > TB) len = TB;
                g_work[w * 3 + 0] = e;
                g_work[w * 3 + 1] = base;
                g_work[w * 3 + 2] = len;
                w++;
            }
        }
        g_nw = w;
    }
}

// ---------------------------------------------------------------------------
// Kernel 3: expert MLP-1, 4-row x 4-token register blocking, SwiGLU in regs.
// grid (2I_/32, MAXW), 256 threads; warp wid -> w1 rows r0 = bx*32 + wid*4
// Rows (r0,r0+1) -> act column r0/2; rows (r0+2,r0+3) -> column r0/2+1.
// ---------------------------------------------------------------------------
__global__ void __launch_bounds__(256, 4) k_mlp1(
    const float* __restrict__ w1, const float* __restrict__ b1)
{
    int widx = blockIdx.y;
    if (widx >= g_nw) return;
    int e    = g_work[widx * 3 + 0];
    int base = g_work[widx * 3 + 1];
    int n    = g_work[widx * 3 + 2];

    __shared__ float tile[TB * H_];   // 12 KB (zero-padded)
    __shared__ int ssel[TB];

    int tid = threadIdx.x, wid = tid >> 5, lane = tid & 31;

    if (tid < TB) ssel[tid] = (tid < n) ? g_sel[e * S_ + base + tid] : 0;
    __syncthreads();
#pragma unroll
    for (int i = 0; i < TB; i++) {
        if (i < n) {
            int s = ssel[i] >> 2;
            for (int j = tid; j < H_; j += 256) tile[i * H_ + j] = g_t[s * H_ + j];
        } else {
            for (int j = tid; j < H_; j += 256) tile[i * H_ + j] = 0.f;
        }
    }
    __syncthreads();

    int r0 = blockIdx.x * 32 + wid * 4;
    const float4* wp = (const float4*)(w1 + ((size_t)e * 2 * I_ + r0) * H_);

    float acc[4][4];
#pragma unroll
    for (int r = 0; r < 4; r++)
#pragma unroll
        for (int i = 0; i < 4; i++) acc[r][i] = 0.f;

    core44(wp, tile, lane, acc);

    float d0 = reduce4(acc[0][0], acc[0][1], acc[0][2], acc[0][3], lane);
    float d1 = reduce4(acc[1][0], acc[1][1], acc[1][2], acc[1][3], lane);
    float d2 = reduce4(acc[2][0], acc[2][1], acc[2][2], acc[2][3], lane);
    float d3 = reduce4(acc[3][0], acc[3][1], acc[3][2], acc[3][3], lane);

    if (lane < n) {
        int sel = ssel[lane];
        int c0 = r0 >> 1;
        const float* bp = b1 + e * 2 * I_ + r0;
        float hg = fminf(d0 + bp[0], LIMIT_);
        float hl = fminf(fmaxf(d1 + bp[1], -LIMIT_), LIMIT_);
        float sig = 1.f / (1.f + __expf(-ALPHA_ * hg));
        g_act[sel * I_ + c0] = hg * sig * (hl + 1.f);

        float hg2 = fminf(d2 + bp[2], LIMIT_);
        float hl2 = fminf(fmaxf(d3 + bp[3], -LIMIT_), LIMIT_);
        float sig2 = 1.f / (1.f + __expf(-ALPHA_ * hg2));
        g_act[sel * I_ + c0 + 1] = hg2 * sig2 * (hl2 + 1.f);
    }
}

// ---------------------------------------------------------------------------
// Kernel 4: expert MLP-2, 4-row x 4-token blocking + weighted accumulation
// grid (H_/32, MAXW), 256 threads; warp wid -> w2 rows c0 = bx*32 + wid*4
// ---------------------------------------------------------------------------
__global__ void __launch_bounds__(256, 4) k_mlp2(
    const float* __restrict__ w2, const float* __restrict__ b2,
    float* __restrict__ out)
{
    int widx = blockIdx.y;
    if (widx >= g_nw) return;
    int e    = g_work[widx * 3 + 0];
    int base = g_work[widx * 3 + 1];
    int n    = g_work[widx * 3 + 2];

    __shared__ float tile[TB * I_];   // 12 KB (zero-padded)
    __shared__ int   ssel[TB];
    __shared__ float swt[TB];

    int tid = threadIdx.x, wid = tid >> 5, lane = tid & 31;

    if (tid < TB) {
        int sel = (tid < n) ? g_sel[e * S_ + base + tid] : 0;
        ssel[tid] = sel;
        swt[tid]  = (tid < n) ? g_wts[sel] : 0.f;
    }
    __syncthreads();
#pragma unroll
    for (int i = 0; i < TB; i++) {
        if (i < n) {
            int sel = ssel[i];
            for (int j = tid; j < I_; j += 256) tile[i * I_ + j] = g_act[sel * I_ + j];
        } else {
            for (int j = tid; j < I_; j += 256) tile[i * I_ + j] = 0.f;
        }
    }
    __syncthreads();

    int c0 = blockIdx.x * 32 + wid * 4;
    const float4* wp = (const float4*)(w2 + ((size_t)e * H_ + c0) * I_);

    float acc[4][4];
#pragma unroll
    for (int r = 0; r < 4; r++)
#pragma unroll
        for (int i = 0; i < 4; i++) acc[r][i] = 0.f;

    core44(wp, tile, lane, acc);

    float d0 = reduce4(acc[0][0], acc[0][1], acc[0][2], acc[0][3], lane);
    float d1 = reduce4(acc[1][0], acc[1][1], acc[1][2], acc[1][3], lane);
    float d2 = reduce4(acc[2][0], acc[2][1], acc[2][2], acc[2][3], lane);
    float d3 = reduce4(acc[3][0], acc[3][1], acc[3][2], acc[3][3], lane);

    if (lane < n) {
        int s = ssel[lane] >> 2;
        float w = swt[lane];
        const float* bp = b2 + e * H_ + c0;
        float* op = out + s * H_ + c0;
        atomicAdd(op + 0, w * (d0 + bp[0]));
        atomicAdd(op + 1, w * (d1 + bp[1]));
        atomicAdd(op + 2, w * (d2 + bp[2]));
        atomicAdd(op + 3, w * (d3 + bp[3]));
    }
}

// ---------------------------------------------------------------------------
extern "C" void kernel_launch(void* const* d_in, const int* in_sizes, int n_in,
                              void* d_out, int out_size)
{
    const float* x  = (const float*)d_in[0];
    const float* ns = (const float*)d_in[1];
    const float* gw = (const float*)d_in[2];
    const float* gb = (const float*)d_in[3];
    const float* w1 = (const float*)d_in[4];
    const float* b1 = (const float*)d_in[5];
    const float* w2 = (const float*)d_in[6];
    const float* b2 = (const float*)d_in[7];
    float* out = (float*)d_out;

    k_norm_router<<<S_, 256>>>(x, ns, gw, gb, out);
    k_build<<<1, 32>>>();
    dim3 g1(2 * I_ / 32, MAXW);   // (48, 64)
    k_mlp1<<<g1, 256>>>(w1, b1);
    dim3 g2(H_ / 32, MAXW);       // (24, 64)
    k_mlp2<<<g2, 256>>>(w2, b2, out);
}

// round 8
// speedup vs baseline: 1.3408x; 1.0554x over previous
#include <cuda_runtime.h>
#include <math.h>

#define S_ 32
#define H_ 768
#define I_ 768
#define E_ 32
#define TOPK_ 4
#define LIMIT_ 7.0f
#define ALPHA_ 1.702f
#define EPS_ 1e-5f

#define TB 4           // tokens per work chunk
#define MAXW 64        // max work chunks
#define NCH 6          // weight chunks per item (768/128)

// Scratch (device globals: allocation-free)
__device__ float g_t[S_ * H_];           // rmsnormed tokens
__device__ int   g_idx[S_ * TOPK_];      // top-k expert ids
__device__ float g_wts[S_ * TOPK_];      // softmax weights
__device__ int   g_cnt[E_];              // tokens per expert
__device__ int   g_sel[E_ * S_];         // sel = s*4+k per expert slot
__device__ float g_act[S_ * TOPK_ * I_]; // post-SwiGLU activations
__device__ int   g_work[MAXW * 3];       // (expert, base, len)
__device__ int   g_nw;

// ---- cp.async helpers ------------------------------------------------------
__device__ __forceinline__ void cp16(void* smem, const void* gmem)
{
    unsigned s = (unsigned)__cvta_generic_to_shared(smem);
    asm volatile("cp.async.cg.shared.global [%0], [%1], 16;" :: "r"(s), "l"(gmem));
}
__device__ __forceinline__ void cp_commit()
{
    asm volatile("cp.async.commit_group;");
}
template<int N>
__device__ __forceinline__ void cp_wait()
{
    asm volatile("cp.async.wait_group %0;" :: "n"(N));
}

// Packed reduction: 4 per-thread partials -> lane L (L<4) holds full sum of a[L].
__device__ __forceinline__ float reduce4(float a0, float a1, float a2, float a3, int lane)
{
    float w0 = (lane & 1) ? a1 : a0;
    float o0 = (lane & 1) ? a0 : a1;
    float b0 = w0 + __shfl_xor_sync(0xffffffffu, o0, 1);
    float w1 = (lane & 1) ? a3 : a2;
    float o1 = (lane & 1) ? a2 : a3;
    float b1 = w1 + __shfl_xor_sync(0xffffffffu, o1, 1);
    float w2 = (lane & 2) ? b1 : b0;
    float o2 = (lane & 2) ? b0 : b1;
    float c  = w2 + __shfl_xor_sync(0xffffffffu, o2, 2);
    c += __shfl_xor_sync(0xffffffffu, c, 4);
    c += __shfl_xor_sync(0xffffffffu, c, 8);
    c += __shfl_xor_sync(0xffffffffu, c, 16);
    return c;
}

// issue one 32-row x 128-col weight chunk into smem buffer (16 KB)
__device__ __forceinline__ void issue_chunk(
    float* wbuf, const float* wbase, int c, int tid)
{
#pragma unroll
    for (int k = 0; k < 4; k++) {
        int idx = tid + 256 * k;      // 0..1023
        int row = idx >> 5;
        int col = idx & 31;           // float4 column within chunk
        cp16(wbuf + ((size_t)row * 32 + col) * 4,
             wbase + (size_t)row * H_ + c * 128 + col * 4);
    }
}

// compute one chunk: 4 rows (this warp) x 4 tokens
__device__ __forceinline__ void chunk_fma(
    const float* wbuf, const float* tile, int c, int wid, int lane,
    float acc[4][4])
{
    const float4* ws = (const float4*)wbuf + (size_t)(wid * 4) * 32 + lane;
    const float4* ts = (const float4*)tile + c * 32 + lane;
    float4 w0 = ws[0], w1 = ws[32], w2 = ws[64], w3 = ws[96];
    float4 t0 = ts[0], t1 = ts[192], t2 = ts[384], t3 = ts[576];

#define FMA4(r, wv, i, tv) \
    acc[r][i] += wv.x * tv.x + wv.y * tv.y + wv.z * tv.z + wv.w * tv.w;
    FMA4(0, w0, 0, t0) FMA4(0, w0, 1, t1) FMA4(0, w0, 2, t2) FMA4(0, w0, 3, t3)
    FMA4(1, w1, 0, t0) FMA4(1, w1, 1, t1) FMA4(1, w1, 2, t2) FMA4(1, w1, 3, t3)
    FMA4(2, w2, 0, t0) FMA4(2, w2, 1, t1) FMA4(2, w2, 2, t2) FMA4(2, w2, 3, t3)
    FMA4(3, w3, 0, t0) FMA4(3, w3, 1, t1) FMA4(3, w3, 2, t2) FMA4(3, w3, 3, t3)
#undef FMA4
}

// ---------------------------------------------------------------------------
// Kernel 1: RMSNorm + router (logits, top-4, softmax) + residual init
// ---------------------------------------------------------------------------
__global__ void __launch_bounds__(256) k_norm_router(
    const float* __restrict__ x, const float* __restrict__ nscale,
    const float* __restrict__ gw, const float* __restrict__ gb,
    float* __restrict__ out)
{
    int s   = blockIdx.x;
    int tid = threadIdx.x;
    int lane = tid & 31, wid = tid >> 5;

    __shared__ float sh_t[H_];
    __shared__ float red[8];
    __shared__ float logits[E_];

    float v0[3];
    float ss = 0.f;
#pragma unroll
    for (int q = 0; q < 3; q++) {
        float v = x[s * H_ + tid + 256 * q];
        v0[q] = v;
        ss += v * v;
    }
#pragma unroll
    for (int o = 16; o; o >>= 1) ss += __shfl_xor_sync(0xffffffffu, ss, o);
    if (lane == 0) red[wid] = ss;
    __syncthreads();
    if (tid < 8) {
        float r = red[tid];
#pragma unroll
        for (int o = 4; o; o >>= 1) r += __shfl_xor_sync(0xffu, r, o);
        if (tid == 0) red[0] = r;
    }
    __syncthreads();
    float rms = rsqrtf(red[0] / (float)H_ + EPS_);

#pragma unroll
    for (int q = 0; q < 3; q++) {
        int j = tid + 256 * q;
        float t = v0[q] * rms * nscale[j];
        sh_t[j] = t;
        g_t[s * H_ + j] = t;
        out[s * H_ + j] = v0[q];   // residual init out = x
    }
    __syncthreads();

#pragma unroll
    for (int e4 = 0; e4 < 4; e4++) {
        int e = wid * 4 + e4;
        float acc = 0.f;
        for (int j = lane; j < H_; j += 32) acc += sh_t[j] * gw[e * H_ + j];
#pragma unroll
        for (int o = 16; o; o >>= 1) acc += __shfl_xor_sync(0xffffffffu, acc, o);
        if (lane == 0) logits[e] = acc + gb[e];
    }
    __syncthreads();

    if (tid == 0) {
        float l[E_];
#pragma unroll
        for (int e = 0; e < E_; e++) l[e] = logits[e];
        float vals[TOPK_];
        int   ids[TOPK_];
#pragma unroll
        for (int k = 0; k < TOPK_; k++) {
            float m = -1e30f; int mi = 0;
            for (int e = 0; e < E_; e++) {
                if (l[e] > m) { m = l[e]; mi = e; }
            }
            vals[k] = m; ids[k] = mi; l[mi] = -1e30f;
        }
        float mx = vals[0], sum = 0.f, w[TOPK_];
#pragma unroll
        for (int k = 0; k < TOPK_; k++) { w[k] = __expf(vals[k] - mx); sum += w[k]; }
        float inv = 1.f / sum;
#pragma unroll
        for (int k = 0; k < TOPK_; k++) {
            g_idx[s * TOPK_ + k] = ids[k];
            g_wts[s * TOPK_ + k] = w[k] * inv;
        }
    }
}

// ---------------------------------------------------------------------------
// Kernel 2: build per-expert selection lists + work chunks (single thread)
// ---------------------------------------------------------------------------
__global__ void k_build()
{
    if (threadIdx.x == 0 && blockIdx.x == 0) {
        for (int e = 0; e < E_; e++) g_cnt[e] = 0;
        for (int sel = 0; sel < S_ * TOPK_; sel++) {
            int e = g_idx[sel];
            g_sel[e * S_ + g_cnt[e]] = sel;
            g_cnt[e]++;
        }
        int w = 0;
        for (int e = 0; e < E_; e++) {
            int n = g_cnt[e];
            for (int base = 0; base < n; base += TB) {
                int len = n - base; if (len > TB) len = TB;
                g_work[w * 3 + 0] = e;
                g_work[w * 3 + 1] = base;
                g_work[w * 3 + 2] = len;
                w++;
            }
        }
        g_nw = w;
    }
}

// ---------------------------------------------------------------------------
// Kernel 3: expert MLP-1 (32 w1 rows/block), cp.async pipelined weights,
//           SwiGLU fused in registers.
// grid (2I_/32, MAXW), 256 threads
// ---------------------------------------------------------------------------
__global__ void __launch_bounds__(256, 4) k_mlp1(
    const float* __restrict__ w1, const float* __restrict__ b1)
{
    int widx = blockIdx.y;
    if (widx >= g_nw) return;
    int e    = g_work[widx * 3 + 0];
    int base = g_work[widx * 3 + 1];
    int n    = g_work[widx * 3 + 2];

    __shared__ float tile[TB * H_];          // 12 KB token tile
    __shared__ float wbuf[2][32 * 128];      // 2 x 16 KB weight chunks

    int tid = threadIdx.x, wid = tid >> 5, lane = tid & 31;

    int r0b = blockIdx.x * 32;
    const float* wbase = w1 + ((size_t)e * 2 * I_ + r0b) * H_;

    // group 0: token tile + weight chunk 0 ; group 1: weight chunk 1
    for (int idx = tid; idx < n * 192; idx += 256) {
        int row = idx / 192, col = idx % 192;
        int s = g_sel[e * S_ + base + row] >> 2;
        cp16(tile + (size_t)idx * 4, g_t + (size_t)s * H_ + col * 4);
    }
    // zero-pad missing token rows
    for (int idx = tid + n * 192; idx < TB * 192; idx += 256)
        ((float4*)tile)[idx] = make_float4(0.f, 0.f, 0.f, 0.f);
    issue_chunk(wbuf[0], wbase, 0, tid);
    cp_commit();
    issue_chunk(wbuf[1], wbase, 1, tid);
    cp_commit();

    float acc[4][4];
#pragma unroll
    for (int r = 0; r < 4; r++)
#pragma unroll
        for (int i = 0; i < 4; i++) acc[r][i] = 0.f;

#pragma unroll
    for (int c = 0; c < NCH; c++) {
        if (c < NCH - 1) cp_wait<1>(); else cp_wait<0>();
        __syncthreads();
        chunk_fma(wbuf[c & 1], tile, c, wid, lane, acc);
        if (c + 2 < NCH) {
            __syncthreads();
            issue_chunk(wbuf[c & 1], wbase, c + 2, tid);
            cp_commit();
        }
    }

    float d0 = reduce4(acc[0][0], acc[0][1], acc[0][2], acc[0][3], lane);
    float d1 = reduce4(acc[1][0], acc[1][1], acc[1][2], acc[1][3], lane);
    float d2 = reduce4(acc[2][0], acc[2][1], acc[2][2], acc[2][3], lane);
    float d3 = reduce4(acc[3][0], acc[3][1], acc[3][2], acc[3][3], lane);

    if (lane < n) {
        int sel = g_sel[e * S_ + base + lane];
        int r0 = r0b + wid * 4;
        int c0 = r0 >> 1;
        const float* bp = b1 + e * 2 * I_ + r0;
        float hg = fminf(d0 + bp[0], LIMIT_);
        float hl = fminf(fmaxf(d1 + bp[1], -LIMIT_), LIMIT_);
        float sig = 1.f / (1.f + __expf(-ALPHA_ * hg));
        g_act[sel * I_ + c0] = hg * sig * (hl + 1.f);

        float hg2 = fminf(d2 + bp[2], LIMIT_);
        float hl2 = fminf(fmaxf(d3 + bp[3], -LIMIT_), LIMIT_);
        float sig2 = 1.f / (1.f + __expf(-ALPHA_ * hg2));
        g_act[sel * I_ + c0 + 1] = hg2 * sig2 * (hl2 + 1.f);
    }
}

// ---------------------------------------------------------------------------
// Kernel 4: expert MLP-2 (32 w2 rows/block), cp.async pipelined weights,
//           weighted accumulation into out.
// grid (H_/32, MAXW), 256 threads
// ---------------------------------------------------------------------------
__global__ void __launch_bounds__(256, 4) k_mlp2(
    const float* __restrict__ w2, const float* __restrict__ b2,
    float* __restrict__ out)
{
    int widx = blockIdx.y;
    if (widx >= g_nw) return;
    int e    = g_work[widx * 3 + 0];
    int base = g_work[widx * 3 + 1];
    int n    = g_work[widx * 3 + 2];

    __shared__ float tile[TB * I_];          // 12 KB act tile
    __shared__ float wbuf[2][32 * 128];      // 2 x 16 KB weight chunks

    int tid = threadIdx.x, wid = tid >> 5, lane = tid & 31;

    int c0b = blockIdx.x * 32;
    const float* wbase = w2 + ((size_t)e * H_ + c0b) * I_;

    for (int idx = tid; idx < n * 192; idx += 256) {
        int row = idx / 192, col = idx % 192;
        int sel = g_sel[e * S_ + base + row];
        cp16(tile + (size_t)idx * 4, g_act + (size_t)sel * I_ + col * 4);
    }
    for (int idx = tid + n * 192; idx < TB * 192; idx += 256)
        ((float4*)tile)[idx] = make_float4(0.f, 0.f, 0.f, 0.f);
    issue_chunk(wbuf[0], wbase, 0, tid);
    cp_commit();
    issue_chunk(wbuf[1], wbase, 1, tid);
    cp_commit();

    float acc[4][4];
#pragma unroll
    for (int r = 0; r < 4; r++)
#pragma unroll
        for (int i = 0; i < 4; i++) acc[r][i] = 0.f;

#pragma unroll
    for (int c = 0; c < NCH; c++) {
        if (c < NCH - 1) cp_wait<1>(); else cp_wait<0>();
        __syncthreads();
        chunk_fma(wbuf[c & 1], tile, c, wid, lane, acc);
        if (c + 2 < NCH) {
            __syncthreads();
            issue_chunk(wbuf[c & 1], wbase, c + 2, tid);
            cp_commit();
        }
    }

    float d0 = reduce4(acc[0][0], acc[0][1], acc[0][2], acc[0][3], lane);
    float d1 = reduce4(acc[1][0], acc[1][1], acc[1][2], acc[1][3], lane);
    float d2 = reduce4(acc[2][0], acc[2][1], acc[2][2], acc[2][3], lane);
    float d3 = reduce4(acc[3][0], acc[3][1], acc[3][2], acc[3][3], lane);

    if (lane < n) {
        int sel = g_sel[e * S_ + base + lane];
        int s = sel >> 2;
        float w = g_wts[sel];
        int c0 = c0b + wid * 4;
        const float* bp = b2 + e * H_ + c0;
        float* op = out + s * H_ + c0;
        atomicAdd(op + 0, w * (d0 + bp[0]));
        atomicAdd(op + 1, w * (d1 + bp[1]));
        atomicAdd(op + 2, w * (d2 + bp[2]));
        atomicAdd(op + 3, w * (d3 + bp[3]));
    }
}

// ---------------------------------------------------------------------------
extern "C" void kernel_launch(void* const* d_in, const int* in_sizes, int n_in,
                              void* d_out, int out_size)
{
    const float* x  = (const float*)d_in[0];
    const float* ns = (const float*)d_in[1];
    const float* gw = (const float*)d_in[2];
    const float* gb = (const float*)d_in[3];
    const float* w1 = (const float*)d_in[4];
    const float* b1 = (const float*)d_in[5];
    const float* w2 = (const float*)d_in[6];
    const float* b2 = (const float*)d_in[7];
    float* out = (float*)d_out;

    k_norm_router<<<S_, 256>>>(x, ns, gw, gb, out);
    k_build<<<1, 32>>>();
    dim3 g1(2 * I_ / 32, MAXW);   // (48, 64)
    k_mlp1<<<g1, 256>>>(w1, b1);
    dim3 g2(H_ / 32, MAXW);       // (24, 64)
    k_mlp2<<<g2, 256>>>(w2, b2, out);
}

// round 9
// speedup vs baseline: 1.4012x; 1.0451x over previous
#include <cuda_runtime.h>
#include <math.h>

#define S_ 32
#define H_ 768
#define I_ 768
#define E_ 32
#define TOPK_ 4
#define LIMIT_ 7.0f
#define ALPHA_ 1.702f
#define EPS_ 1e-5f

#define TB 4           // tokens per work chunk
#define MAXW 64        // max work chunks
#define NCH 6          // weight column-chunks (768/128)

// Scratch (device globals: allocation-free)
__device__ float g_t[S_ * H_];           // rmsnormed tokens
__device__ int   g_idx[S_ * TOPK_];      // top-k expert ids
__device__ float g_wts[S_ * TOPK_];      // softmax weights
__device__ int   g_cnt[E_];              // tokens per expert
__device__ int   g_sel[E_ * S_];         // sel = s*4+k per expert slot
__device__ float g_act[S_ * TOPK_ * I_]; // post-SwiGLU activations
__device__ int   g_work[MAXW * 3];       // (expert, base, len)
__device__ int   g_nw;

// ---- cp.async helpers ------------------------------------------------------
__device__ __forceinline__ void cp16(void* smem, const void* gmem)
{
    unsigned s = (unsigned)__cvta_generic_to_shared(smem);
    asm volatile("cp.async.cg.shared.global [%0], [%1], 16;" :: "r"(s), "l"(gmem));
}
__device__ __forceinline__ void cp_commit()
{
    asm volatile("cp.async.commit_group;");
}
template<int N>
__device__ __forceinline__ void cp_wait()
{
    asm volatile("cp.async.wait_group %0;" :: "n"(N));
}

// Packed reduction: 4 per-thread partials -> lane L (L<4) holds full sum of a[L].
__device__ __forceinline__ float reduce4(float a0, float a1, float a2, float a3, int lane)
{
    float w0 = (lane & 1) ? a1 : a0;
    float o0 = (lane & 1) ? a0 : a1;
    float b0 = w0 + __shfl_xor_sync(0xffffffffu, o0, 1);
    float w1 = (lane & 1) ? a3 : a2;
    float o1 = (lane & 1) ? a2 : a3;
    float b1 = w1 + __shfl_xor_sync(0xffffffffu, o1, 1);
    float w2 = (lane & 2) ? b1 : b0;
    float o2 = (lane & 2) ? b0 : b1;
    float c  = w2 + __shfl_xor_sync(0xffffffffu, o2, 2);
    c += __shfl_xor_sync(0xffffffffu, c, 4);
    c += __shfl_xor_sync(0xffffffffu, c, 8);
    c += __shfl_xor_sync(0xffffffffu, c, 16);
    return c;
}

// Per-warp: issue this warp's 4 rows, column-chunk c, into its private buffer.
// buf points at 128 float4 (2 KB). wrow = warp's row base pointer.
__device__ __forceinline__ void issue_warp_chunk(
    float4* buf, const float* wrow, int c, int lane)
{
#pragma unroll
    for (int r = 0; r < 4; r++)
        cp16(buf + r * 32 + lane, wrow + (size_t)r * H_ + c * 128 + lane * 4);
    cp_commit();
}

// compute one chunk: this warp's 4 rows x 4 tokens
__device__ __forceinline__ void chunk_fma(
    const float4* buf, const float* tile, int c, int lane, float acc[4][4])
{
    const float4* ts = (const float4*)tile + c * 32 + lane;
    float4 w0 = buf[lane], w1 = buf[32 + lane], w2 = buf[64 + lane], w3 = buf[96 + lane];
    float4 t0 = ts[0], t1 = ts[192], t2 = ts[384], t3 = ts[576];

#define FMA4(r, wv, i, tv) \
    acc[r][i] += wv.x * tv.x + wv.y * tv.y + wv.z * tv.z + wv.w * tv.w;
    FMA4(0, w0, 0, t0) FMA4(0, w0, 1, t1) FMA4(0, w0, 2, t2) FMA4(0, w0, 3, t3)
    FMA4(1, w1, 0, t0) FMA4(1, w1, 1, t1) FMA4(1, w1, 2, t2) FMA4(1, w1, 3, t3)
    FMA4(2, w2, 0, t0) FMA4(2, w2, 1, t1) FMA4(2, w2, 2, t2) FMA4(2, w2, 3, t3)
    FMA4(3, w3, 0, t0) FMA4(3, w3, 1, t1) FMA4(3, w3, 2, t2) FMA4(3, w3, 3, t3)
#undef FMA4
}

// ---------------------------------------------------------------------------
// Kernel 1: RMSNorm + router (logits, top-4, softmax) + residual init
// ---------------------------------------------------------------------------
__global__ void __launch_bounds__(256) k_norm_router(
    const float* __restrict__ x, const float* __restrict__ nscale,
    const float* __restrict__ gw, const float* __restrict__ gb,
    float* __restrict__ out)
{
    int s   = blockIdx.x;
    int tid = threadIdx.x;
    int lane = tid & 31, wid = tid >> 5;

    __shared__ float sh_t[H_];
    __shared__ float red[8];
    __shared__ float logits[E_];

    float v0[3];
    float ss = 0.f;
#pragma unroll
    for (int q = 0; q < 3; q++) {
        float v = x[s * H_ + tid + 256 * q];
        v0[q] = v;
        ss += v * v;
    }
#pragma unroll
    for (int o = 16; o; o >>= 1) ss += __shfl_xor_sync(0xffffffffu, ss, o);
    if (lane == 0) red[wid] = ss;
    __syncthreads();
    if (tid < 8) {
        float r = red[tid];
#pragma unroll
        for (int o = 4; o; o >>= 1) r += __shfl_xor_sync(0xffu, r, o);
        if (tid == 0) red[0] = r;
    }
    __syncthreads();
    float rms = rsqrtf(red[0] / (float)H_ + EPS_);

#pragma unroll
    for (int q = 0; q < 3; q++) {
        int j = tid + 256 * q;
        float t = v0[q] * rms * nscale[j];
        sh_t[j] = t;
        g_t[s * H_ + j] = t;
        out[s * H_ + j] = v0[q];   // residual init out = x
    }
    __syncthreads();

#pragma unroll
    for (int e4 = 0; e4 < 4; e4++) {
        int e = wid * 4 + e4;
        float acc = 0.f;
        for (int j = lane; j < H_; j += 32) acc += sh_t[j] * gw[e * H_ + j];
#pragma unroll
        for (int o = 16; o; o >>= 1) acc += __shfl_xor_sync(0xffffffffu, acc, o);
        if (lane == 0) logits[e] = acc + gb[e];
    }
    __syncthreads();

    if (tid == 0) {
        float l[E_];
#pragma unroll
        for (int e = 0; e < E_; e++) l[e] = logits[e];
        float vals[TOPK_];
        int   ids[TOPK_];
#pragma unroll
        for (int k = 0; k < TOPK_; k++) {
            float m = -1e30f; int mi = 0;
            for (int e = 0; e < E_; e++) {
                if (l[e] > m) { m = l[e]; mi = e; }
            }
            vals[k] = m; ids[k] = mi; l[mi] = -1e30f;
        }
        float mx = vals[0], sum = 0.f, w[TOPK_];
#pragma unroll
        for (int k = 0; k < TOPK_; k++) { w[k] = __expf(vals[k] - mx); sum += w[k]; }
        float inv = 1.f / sum;
#pragma unroll
        for (int k = 0; k < TOPK_; k++) {
            g_idx[s * TOPK_ + k] = ids[k];
            g_wts[s * TOPK_ + k] = w[k] * inv;
        }
    }
}

// ---------------------------------------------------------------------------
// Kernel 2: build per-expert selection lists + work chunks (single thread)
// ---------------------------------------------------------------------------
__global__ void k_build()
{
    if (threadIdx.x == 0 && blockIdx.x == 0) {
        for (int e = 0; e < E_; e++) g_cnt[e] = 0;
        for (int sel = 0; sel < S_ * TOPK_; sel++) {
            int e = g_idx[sel];
            g_sel[e * S_ + g_cnt[e]] = sel;
            g_cnt[e]++;
        }
        int w = 0;
        for (int e = 0; e < E_; e++) {
            int n = g_cnt[e];
            for (int base = 0; base < n; base += TB) {
                int len = n - base; if (len > TB) len = TB;
                g_work[w * 3 + 0] = e;
                g_work[w * 3 + 1] = base;
                g_work[w * 3 + 2] = len;
                w++;
            }
        }
        g_nw = w;
    }
}

// ---------------------------------------------------------------------------
// Kernel 3: expert MLP-1 (32 w1 rows/block), warp-private cp.async pipeline,
//           SwiGLU fused in registers. Zero block barriers in main loop.
// grid (2I_/32, MAXW), 256 threads
// ---------------------------------------------------------------------------
__global__ void __launch_bounds__(256, 4) k_mlp1(
    const float* __restrict__ w1, const float* __restrict__ b1)
{
    int widx = blockIdx.y;
    if (widx >= g_nw) return;
    int e    = g_work[widx * 3 + 0];
    int base = g_work[widx * 3 + 1];
    int n    = g_work[widx * 3 + 2];

    __shared__ float tile[TB * H_];          // 12 KB token tile
    __shared__ float4 wbuf[8][2][128];       // per-warp 2-stage, 32 KB total

    int tid = threadIdx.x, wid = tid >> 5, lane = tid & 31;

    // token tile (regular loads; one barrier)
    for (int idx = tid; idx < TB * 192; idx += 256) {
        int row = idx / 192, col = idx % 192;
        float4 v = make_float4(0.f, 0.f, 0.f, 0.f);
        if (row < n) {
            int s = g_sel[e * S_ + base + row] >> 2;
            v = *(const float4*)(g_t + (size_t)s * H_ + col * 4);
        }
        ((float4*)tile)[idx] = v;
    }

    int r0 = blockIdx.x * 32 + wid * 4;
    const float* wrow = w1 + ((size_t)e * 2 * I_ + r0) * H_;

    issue_warp_chunk(wbuf[wid][0], wrow, 0, lane);
    issue_warp_chunk(wbuf[wid][1], wrow, 1, lane);

    __syncthreads();    // tile ready

    float acc[4][4];
#pragma unroll
    for (int r = 0; r < 4; r++)
#pragma unroll
        for (int i = 0; i < 4; i++) acc[r][i] = 0.f;

#pragma unroll
    for (int c = 0; c < NCH; c++) {
        if (c < NCH - 1) cp_wait<1>(); else cp_wait<0>();
        __syncwarp();
        chunk_fma(wbuf[wid][c & 1], tile, c, lane, acc);
        if (c + 2 < NCH) {
            __syncwarp();
            issue_warp_chunk(wbuf[wid][c & 1], wrow, c + 2, lane);
        }
    }

    float d0 = reduce4(acc[0][0], acc[0][1], acc[0][2], acc[0][3], lane);
    float d1 = reduce4(acc[1][0], acc[1][1], acc[1][2], acc[1][3], lane);
    float d2 = reduce4(acc[2][0], acc[2][1], acc[2][2], acc[2][3], lane);
    float d3 = reduce4(acc[3][0], acc[3][1], acc[3][2], acc[3][3], lane);

    if (lane < n) {
        int sel = g_sel[e * S_ + base + lane];
        int c0 = r0 >> 1;
        const float* bp = b1 + e * 2 * I_ + r0;
        float hg = fminf(d0 + bp[0], LIMIT_);
        float hl = fminf(fmaxf(d1 + bp[1], -LIMIT_), LIMIT_);
        float sig = 1.f / (1.f + __expf(-ALPHA_ * hg));
        g_act[sel * I_ + c0] = hg * sig * (hl + 1.f);

        float hg2 = fminf(d2 + bp[2], LIMIT_);
        float hl2 = fminf(fmaxf(d3 + bp[3], -LIMIT_), LIMIT_);
        float sig2 = 1.f / (1.f + __expf(-ALPHA_ * hg2));
        g_act[sel * I_ + c0 + 1] = hg2 * sig2 * (hl2 + 1.f);
    }
}

// ---------------------------------------------------------------------------
// Kernel 4: expert MLP-2 (32 w2 rows/block), warp-private cp.async pipeline,
//           weighted accumulation into out.
// grid (H_/32, MAXW), 256 threads
// ---------------------------------------------------------------------------
__global__ void __launch_bounds__(256, 4) k_mlp2(
    const float* __restrict__ w2, const float* __restrict__ b2,
    float* __restrict__ out)
{
    int widx = blockIdx.y;
    if (widx >= g_nw) return;
    int e    = g_work[widx * 3 + 0];
    int base = g_work[widx * 3 + 1];
    int n    = g_work[widx * 3 + 2];

    __shared__ float tile[TB * I_];          // 12 KB act tile
    __shared__ float4 wbuf[8][2][128];       // per-warp 2-stage, 32 KB total

    int tid = threadIdx.x, wid = tid >> 5, lane = tid & 31;

    for (int idx = tid; idx < TB * 192; idx += 256) {
        int row = idx / 192, col = idx % 192;
        float4 v = make_float4(0.f, 0.f, 0.f, 0.f);
        if (row < n) {
            int sel = g_sel[e * S_ + base + row];
            v = *(const float4*)(g_act + (size_t)sel * I_ + col * 4);
        }
        ((float4*)tile)[idx] = v;
    }

    int c0 = blockIdx.x * 32 + wid * 4;
    const float* wrow = w2 + ((size_t)e * H_ + c0) * I_;

    issue_warp_chunk(wbuf[wid][0], wrow, 0, lane);
    issue_warp_chunk(wbuf[wid][1], wrow, 1, lane);

    __syncthreads();    // tile ready

    float acc[4][4];
#pragma unroll
    for (int r = 0; r < 4; r++)
#pragma unroll
        for (int i = 0; i < 4; i++) acc[r][i] = 0.f;

#pragma unroll
    for (int c = 0; c < NCH; c++) {
        if (c < NCH - 1) cp_wait<1>(); else cp_wait<0>();
        __syncwarp();
        chunk_fma(wbuf[wid][c & 1], tile, c, lane, acc);
        if (c + 2 < NCH) {
            __syncwarp();
            issue_warp_chunk(wbuf[wid][c & 1], wrow, c + 2, lane);
        }
    }

    float d0 = reduce4(acc[0][0], acc[0][1], acc[0][2], acc[0][3], lane);
    float d1 = reduce4(acc[1][0], acc[1][1], acc[1][2], acc[1][3], lane);
    float d2 = reduce4(acc[2][0], acc[2][1], acc[2][2], acc[2][3], lane);
    float d3 = reduce4(acc[3][0], acc[3][1], acc[3][2], acc[3][3], lane);

    if (lane < n) {
        int sel = g_sel[e * S_ + base + lane];
        int s = sel >> 2;
        float w = g_wts[sel];
        const float* bp = b2 + e * H_ + c0;
        float* op = out + s * H_ + c0;
        atomicAdd(op + 0, w * (d0 + bp[0]));
        atomicAdd(op + 1, w * (d1 + bp[1]));
        atomicAdd(op + 2, w * (d2 + bp[2]));
        atomicAdd(op + 3, w * (d3 + bp[3]));
    }
}

// ---------------------------------------------------------------------------
extern "C" void kernel_launch(void* const* d_in, const int* in_sizes, int n_in,
                              void* d_out, int out_size)
{
    const float* x  = (const float*)d_in[0];
    const float* ns = (const float*)d_in[1];
    const float* gw = (const float*)d_in[2];
    const float* gb = (const float*)d_in[3];
    const float* w1 = (const float*)d_in[4];
    const float* b1 = (const float*)d_in[5];
    const float* w2 = (const float*)d_in[6];
    const float* b2 = (const float*)d_in[7];
    float* out = (float*)d_out;

    k_norm_router<<<S_, 256>>>(x, ns, gw, gb, out);
    k_build<<<1, 32>>>();
    dim3 g1(2 * I_ / 32, MAXW);   // (48, 64)
    k_mlp1<<<g1, 256>>>(w1, b1);
    dim3 g2(H_ / 32, MAXW);       // (24, 64)
    k_mlp2<<<g2, 256>>>(w2, b2, out);
}